// round 4
// baseline (speedup 1.0000x reference)
#include <cuda_runtime.h>
#include <cuda_bf16.h>
#include <cstdint>

// ---------------------------------------------------------------------------
// cross_set_score, TF32 pipeline:
//  K1: H[tile,head] = x[tile] @ W1_head      (tf32 mma, fp32 accum, rna-rounded)
//  K2: S[pair,head] = sum leakyrelu(A@B^T)   (tf32 mma, fused reduce)
//  K3: out = (S @ W2) / (8 * nItem_i * nItem_j), symmetric fill
// ---------------------------------------------------------------------------

#define NSET  16
#define MITEM 256
#define DIN   128
#define NHEAD 8
#define DHEAD 64
#define NPAIR 136

#define XSTR  132     // 32-bit smem stride for 128-wide tiles (+4 pad)
#define HSTR  68      // 32-bit smem stride for 64-wide tiles  (+4 pad)

__device__ float g_H[NSET * NSET * NHEAD * MITEM * DHEAD];   // 134 MB scratch
__device__ float g_scratch[NPAIR * NHEAD];

// ---------------- PTX helpers ----------------
// tf32 value lives in a .b32 register (valid fp32 bit pattern, low mantissa zeroed)
__device__ __forceinline__ uint32_t tf32_rna(float v) {
    uint32_t o;
    asm("cvt.rna.tf32.f32 %0, %1;" : "=r"(o) : "f"(v));
    return o;
}
// tf32 mma: A/B operands are .b32 registers, C/D are .f32
__device__ __forceinline__ void mma_tf32(float* c, const uint32_t* a, const uint32_t* b) {
    asm volatile(
        "mma.sync.aligned.m16n8k8.row.col.f32.tf32.tf32.f32 "
        "{%0,%1,%2,%3}, {%4,%5,%6,%7}, {%8,%9}, {%0,%1,%2,%3};"
        : "+f"(c[0]), "+f"(c[1]), "+f"(c[2]), "+f"(c[3])
        : "r"(a[0]), "r"(a[1]), "r"(a[2]), "r"(a[3]), "r"(b[0]), "r"(b[1]));
}

// ============================================================================
// Kernel 1: projection.  blockIdx.x = tile*8 + head.  256 threads.
// H_tile_head[m][e] = sum_d x[tile][m][d] * W1[d][head*64+e]
// ============================================================================
__global__ __launch_bounds__(256, 1)
void proj_kernel(const float* __restrict__ x, const float* __restrict__ W1)
{
    extern __shared__ uint32_t sm1[];
    uint32_t* xs  = sm1;                       // [256][XSTR]
    uint32_t* w1s = sm1 + MITEM * XSTR;        // [64][XSTR]   (n-major, k inner)

    const int tile = blockIdx.x >> 3;
    const int head = blockIdx.x & 7;
    const int tid  = threadIdx.x;
    const int wid  = tid >> 5;
    const int lane = tid & 31;
    const int r    = lane >> 2;
    const int c    = lane & 3;

    // load x tile (fp32 -> tf32-rounded bits) : 256x128
    {
        const float4* g = (const float4*)(x + (size_t)tile * MITEM * DIN);
        #pragma unroll 4
        for (int idx = tid; idx < MITEM * DIN / 4; idx += 256) {
            float4 v = g[idx];
            int row = idx >> 5, cc = (idx & 31) << 2;
            uint32_t* d = &xs[row * XSTR + cc];
            d[0] = tf32_rna(v.x); d[1] = tf32_rna(v.y);
            d[2] = tf32_rna(v.z); d[3] = tf32_rna(v.w);
        }
    }
    // load W1 head slice transposed: w1s[e][d] = W1[d][head*64+e]
    for (int idx = tid; idx < DIN * DHEAD; idx += 256) {
        int d = idx >> 6, e = idx & 63;
        w1s[e * XSTR + d] = tf32_rna(W1[d * (NHEAD * DHEAD) + head * DHEAD + e]);
    }
    __syncthreads();

    // warp tile: 64 rows x 32 cols ; warps (4 m) x (2 n)
    const int wm = (wid & 3) * 64;
    const int wn = (wid >> 2) * 32;

    float acc[4][4][4];
    #pragma unroll
    for (int mt = 0; mt < 4; ++mt)
        #pragma unroll
        for (int nt = 0; nt < 4; ++nt)
            #pragma unroll
            for (int e = 0; e < 4; ++e) acc[mt][nt][e] = 0.f;

    #pragma unroll
    for (int ks = 0; ks < 16; ++ks) {
        const int k0 = ks * 8;
        uint32_t af[4][4], bf[4][2];
        #pragma unroll
        for (int mt = 0; mt < 4; ++mt) {
            const uint32_t* base = &xs[(wm + mt * 16 + r) * XSTR + k0 + c];
            af[mt][0] = base[0];
            af[mt][1] = base[8 * XSTR];
            af[mt][2] = base[4];
            af[mt][3] = base[8 * XSTR + 4];
        }
        #pragma unroll
        for (int nt = 0; nt < 4; ++nt) {
            const uint32_t* base = &w1s[(wn + nt * 8 + r) * XSTR + k0 + c];
            bf[nt][0] = base[0];
            bf[nt][1] = base[4];
        }
        #pragma unroll
        for (int mt = 0; mt < 4; ++mt)
            #pragma unroll
            for (int nt = 0; nt < 4; ++nt)
                mma_tf32(acc[mt][nt], af[mt], bf[nt]);
    }

    // store H (rounded to tf32 bits so K2 needs no cvt; bits are valid fp32)
    float* Hout = g_H + (size_t)(tile * NHEAD + head) * MITEM * DHEAD;
    #pragma unroll
    for (int mt = 0; mt < 4; ++mt)
        #pragma unroll
        for (int nt = 0; nt < 4; ++nt) {
            int row = wm + mt * 16 + r;
            int col = wn + nt * 8 + c * 2;
            float2 lo = { __uint_as_float(tf32_rna(acc[mt][nt][0])),
                          __uint_as_float(tf32_rna(acc[mt][nt][1])) };
            float2 hi = { __uint_as_float(tf32_rna(acc[mt][nt][2])),
                          __uint_as_float(tf32_rna(acc[mt][nt][3])) };
            *(float2*)&Hout[row * DHEAD + col]       = lo;
            *(float2*)&Hout[(row + 8) * DHEAD + col] = hi;
        }
}

// ============================================================================
// Kernel 2: score.  blockIdx.x = pair*8 + head.  256 threads.
// S = sum_{m,n} leakyrelu( A @ B^T )  with A = H[jj,ii,head], B = H[ii,jj,head]
// ============================================================================
__global__ __launch_bounds__(256, 1)
void score_kernel()
{
    extern __shared__ uint32_t sm2[];
    uint32_t* As  = sm2;                        // [256][HSTR]
    uint32_t* Bs  = sm2 + MITEM * HSTR;         // [256][HSTR]
    float*    red = (float*)(sm2 + 2 * MITEM * HSTR);   // [8]

    const int pair = blockIdx.x >> 3;
    const int head = blockIdx.x & 7;
    const int tid  = threadIdx.x;
    const int wid  = tid >> 5;
    const int lane = tid & 31;
    const int r    = lane >> 2;
    const int c    = lane & 3;

    // pair -> (ii <= jj)
    int q = pair, jj = 0;
    while (q >= jj + 1) { q -= (jj + 1); ++jj; }
    const int ii = q;

    // load A, B tiles (contiguous 256x64, already tf32-rounded bits)
    {
        const uint4* gA = (const uint4*)(g_H + (size_t)((jj * NSET + ii) * NHEAD + head) * MITEM * DHEAD);
        const uint4* gB = (const uint4*)(g_H + (size_t)((ii * NSET + jj) * NHEAD + head) * MITEM * DHEAD);
        #pragma unroll 4
        for (int idx = tid; idx < MITEM * DHEAD / 4; idx += 256) {
            uint4 va = gA[idx];
            uint4 vb = gB[idx];
            int row = idx >> 4, cc = (idx & 15) << 2;
            *(uint4*)&As[row * HSTR + cc] = va;
            *(uint4*)&Bs[row * HSTR + cc] = vb;
        }
    }
    __syncthreads();

    // warp tile: 64 rows x 128 cols ; warps (4 m) x (2 n)
    const int wm = (wid & 3) * 64;
    const int wn = (wid >> 2) * 128;

    // A fragments resident: 4 m-tiles x 8 k-steps x 4 regs
    uint32_t aF[4][8][4];
    #pragma unroll
    for (int mt = 0; mt < 4; ++mt)
        #pragma unroll
        for (int ks = 0; ks < 8; ++ks) {
            const uint32_t* base = &As[(wm + mt * 16 + r) * HSTR + ks * 8 + c];
            aF[mt][ks][0] = base[0];
            aF[mt][ks][1] = base[8 * HSTR];
            aF[mt][ks][2] = base[4];
            aF[mt][ks][3] = base[8 * HSTR + 4];
        }

    float sum = 0.f;
    #pragma unroll
    for (int nt = 0; nt < 16; ++nt) {
        uint32_t bF[8][2];
        #pragma unroll
        for (int ks = 0; ks < 8; ++ks) {
            const uint32_t* base = &Bs[(wn + nt * 8 + r) * HSTR + ks * 8 + c];
            bF[ks][0] = base[0];
            bF[ks][1] = base[4];
        }
        #pragma unroll
        for (int mt = 0; mt < 4; ++mt) {
            float cc[4] = {0.f, 0.f, 0.f, 0.f};
            #pragma unroll
            for (int ks = 0; ks < 8; ++ks)
                mma_tf32(cc, aF[mt][ks], bF[ks]);
            #pragma unroll
            for (int e = 0; e < 4; ++e) {
                float v = cc[e];
                sum += (v > 0.f) ? v : 0.3f * v;     // LeakyReLU(0.3)
            }
        }
    }

    // CTA reduce
    #pragma unroll
    for (int off = 16; off; off >>= 1)
        sum += __shfl_xor_sync(0xffffffffu, sum, off);
    if (lane == 0) red[wid] = sum;
    __syncthreads();
    if (tid == 0) {
        float t = 0.f;
        #pragma unroll
        for (int w = 0; w < 8; ++w) t += red[w];
        g_scratch[pair * NHEAD + head] = t;
    }
}

// ============================================================================
// Kernel 3: finalize
// ============================================================================
__global__ void finalize_kernel(const float* __restrict__ nItem,
                                const float* __restrict__ W2,
                                float* __restrict__ out)
{
    const int t = threadIdx.x;       // t = j*16 + i
    const int j = t >> 4, i = t & 15;
    const int a = (j > i) ? j : i;
    const int b = (j > i) ? i : j;
    const int p = a * (a + 1) / 2 + b;
    float s = 0.f;
    #pragma unroll
    for (int hh = 0; hh < NHEAD; ++hh)
        s += g_scratch[p * NHEAD + hh] * W2[hh];
    out[t] = s / (8.0f * nItem[i] * nItem[j]);   // 8 = sqrt(D=64)
}

// ---------------- entry point ----------------
#define SMEM_K1 ((MITEM * XSTR + DHEAD * XSTR) * 4)          // 168960
#define SMEM_K2 ((2 * MITEM * HSTR + 32) * 4)                // 139392

extern "C" void kernel_launch(void* const* d_in, const int* in_sizes, int n_in,
                              void* d_out, int out_size)
{
    const float* x = nullptr;
    const float* nItem = nullptr;
    const float* W1 = nullptr;
    const float* W2 = nullptr;
    for (int k = 0; k < n_in; ++k) {
        switch (in_sizes[k]) {
            case NSET * NSET * MITEM * DIN: x     = (const float*)d_in[k]; break;
            case NSET:                      nItem = (const float*)d_in[k]; break;
            case DIN * NHEAD * DHEAD:       W1    = (const float*)d_in[k]; break;
            case NHEAD:                     W2    = (const float*)d_in[k]; break;
        }
    }

    static bool attr_done = false;
    if (!attr_done) {
        cudaFuncSetAttribute(proj_kernel,
                             cudaFuncAttributeMaxDynamicSharedMemorySize, SMEM_K1);
        cudaFuncSetAttribute(score_kernel,
                             cudaFuncAttributeMaxDynamicSharedMemorySize, SMEM_K2);
        attr_done = true;
    }

    proj_kernel<<<NSET * NSET * NHEAD, 256, SMEM_K1>>>(x, W1);
    score_kernel<<<NPAIR * NHEAD, 256, SMEM_K2>>>();
    finalize_kernel<<<1, 256>>>(nItem, W2, (float*)d_out);
}

// round 5
// speedup vs baseline: 1.2876x; 1.2876x over previous
#include <cuda_runtime.h>
#include <cuda_bf16.h>
#include <cstdint>

// ---------------------------------------------------------------------------
// cross_set_score, TF32 pipeline (v2: 2 CTAs/SM on both heavy kernels):
//  K1: H[tile,head] = x[tile] @ W1_head   (one CTA = 128 rows x 4 heads)
//  K2: S[pair,head] = sum leakyrelu(A@B^T) (one CTA = full A x half B)
//  K3: out = (S @ W2) / (8 * nItem_i * nItem_j), symmetric fill
// ---------------------------------------------------------------------------

#define NSET  16
#define MITEM 256
#define DIN   128
#define NHEAD 8
#define DHEAD 64
#define NPAIR 136

#define XSTR  132     // 32-bit smem stride for 128-wide tiles (+4 pad)
#define HSTR  68      // 32-bit smem stride for 64-wide tiles  (+4 pad)

__device__ float g_H[NSET * NSET * NHEAD * MITEM * DHEAD];   // 134 MB scratch
__device__ float g_scratch[NPAIR * NHEAD * 2];               // 2 N-halves per (pair,head)

// ---------------- PTX helpers ----------------
__device__ __forceinline__ uint32_t tf32_rna(float v) {
    uint32_t o;
    asm("cvt.rna.tf32.f32 %0, %1;" : "=r"(o) : "f"(v));
    return o;
}
__device__ __forceinline__ void mma_tf32(float* c, const uint32_t* a, const uint32_t* b) {
    asm volatile(
        "mma.sync.aligned.m16n8k8.row.col.f32.tf32.tf32.f32 "
        "{%0,%1,%2,%3}, {%4,%5,%6,%7}, {%8,%9}, {%0,%1,%2,%3};"
        : "+f"(c[0]), "+f"(c[1]), "+f"(c[2]), "+f"(c[3])
        : "r"(a[0]), "r"(a[1]), "r"(a[2]), "r"(a[3]), "r"(b[0]), "r"(b[1]));
}

// ============================================================================
// Kernel 1: projection.  grid = 256 tiles * 2 row-halves * 2 head-groups.
// Each CTA: 128 rows of one x tile  x  4 heads.  SMEM ~101KB -> 2 CTAs/SM.
// ============================================================================
__global__ __launch_bounds__(256, 2)
void proj_kernel(const float* __restrict__ x, const float* __restrict__ W1)
{
    extern __shared__ uint32_t sm1[];
    uint32_t* xs  = sm1;                    // [128][XSTR]
    uint32_t* w1s = sm1 + 128 * XSTR;       // [64][XSTR]  (one head, n-major)

    const int bx   = blockIdx.x;
    const int tile = bx >> 2;
    const int rh   = (bx >> 1) & 1;         // row half: 0 or 1
    const int hg   = bx & 1;                // head group: heads hg*4 .. hg*4+3
    const int tid  = threadIdx.x;
    const int wid  = tid >> 5;
    const int lane = tid & 31;
    const int r    = lane >> 2;
    const int c    = lane & 3;

    // ---- load x half-tile (fp32 -> tf32 bits): 128 x 128 ----
    {
        const float4* g = (const float4*)(x + ((size_t)tile * MITEM + rh * 128) * DIN);
        #pragma unroll 4
        for (int idx = tid; idx < 128 * DIN / 4; idx += 256) {
            float4 v = g[idx];
            int row = idx >> 5, cc = (idx & 31) << 2;
            uint32_t* d = &xs[row * XSTR + cc];
            d[0] = tf32_rna(v.x); d[1] = tf32_rna(v.y);
            d[2] = tf32_rna(v.z); d[3] = tf32_rna(v.w);
        }
    }
    // ---- load W1 slice for first head ----
    {
        const int head = hg * 4;
        for (int idx = tid; idx < DIN * DHEAD; idx += 256) {
            int d = idx >> 6, e = idx & 63;
            w1s[e * XSTR + d] = tf32_rna(W1[d * (NHEAD * DHEAD) + head * DHEAD + e]);
        }
    }
    __syncthreads();

    // warp tile: 32 rows x 32 cols; warps (4 m) x (2 n) cover 128 x 64
    const int wm = (wid & 3) * 32;
    const int wn = (wid >> 2) * 32;

    #pragma unroll 1
    for (int h = 0; h < 4; ++h) {
        const int head = hg * 4 + h;

        float acc[2][4][4];
        #pragma unroll
        for (int mt = 0; mt < 2; ++mt)
            #pragma unroll
            for (int nt = 0; nt < 4; ++nt)
                #pragma unroll
                for (int e = 0; e < 4; ++e) acc[mt][nt][e] = 0.f;

        #pragma unroll
        for (int ks = 0; ks < 16; ++ks) {
            const int k0 = ks * 8;
            uint32_t af[2][4], bf[4][2];
            #pragma unroll
            for (int mt = 0; mt < 2; ++mt) {
                const uint32_t* base = &xs[(wm + mt * 16 + r) * XSTR + k0 + c];
                af[mt][0] = base[0];
                af[mt][1] = base[8 * XSTR];
                af[mt][2] = base[4];
                af[mt][3] = base[8 * XSTR + 4];
            }
            #pragma unroll
            for (int nt = 0; nt < 4; ++nt) {
                const uint32_t* base = &w1s[(wn + nt * 8 + r) * XSTR + k0 + c];
                bf[nt][0] = base[0];
                bf[nt][1] = base[4];
            }
            #pragma unroll
            for (int mt = 0; mt < 2; ++mt)
                #pragma unroll
                for (int nt = 0; nt < 4; ++nt)
                    mma_tf32(acc[mt][nt], af[mt], bf[nt]);
        }

        // store H for this head (tf32-rounded bits; valid fp32)
        float* Hout = g_H + (size_t)(tile * NHEAD + head) * MITEM * DHEAD;
        #pragma unroll
        for (int mt = 0; mt < 2; ++mt)
            #pragma unroll
            for (int nt = 0; nt < 4; ++nt) {
                int row = rh * 128 + wm + mt * 16 + r;
                int col = wn + nt * 8 + c * 2;
                float2 lo = { __uint_as_float(tf32_rna(acc[mt][nt][0])),
                              __uint_as_float(tf32_rna(acc[mt][nt][1])) };
                float2 hi = { __uint_as_float(tf32_rna(acc[mt][nt][2])),
                              __uint_as_float(tf32_rna(acc[mt][nt][3])) };
                *(float2*)&Hout[row * DHEAD + col]       = lo;
                *(float2*)&Hout[(row + 8) * DHEAD + col] = hi;
            }

        // load next head's W1 slice
        if (h < 3) {
            __syncthreads();                 // all warps done reading w1s
            const int nhd = head + 1;
            for (int idx = tid; idx < DIN * DHEAD; idx += 256) {
                int d = idx >> 6, e = idx & 63;
                w1s[e * XSTR + d] = tf32_rna(W1[d * (NHEAD * DHEAD) + nhd * DHEAD + e]);
            }
            __syncthreads();
        }
    }
}

// ============================================================================
// Kernel 2: score.  grid = 136 pairs * 8 heads * 2 N-halves.
// CTA: full A (256x64) x half B (128x64).  SMEM ~104KB -> 2 CTAs/SM.
// ============================================================================
__global__ __launch_bounds__(256, 2)
void score_kernel()
{
    extern __shared__ uint32_t sm2[];
    uint32_t* As  = sm2;                          // [256][HSTR]
    uint32_t* Bs  = sm2 + MITEM * HSTR;           // [128][HSTR]
    float*    red = (float*)(sm2 + MITEM * HSTR + 128 * HSTR);   // [8]

    const int bx   = blockIdx.x;
    const int pair = bx >> 4;
    const int head = (bx >> 1) & 7;
    const int nh   = bx & 1;                      // which 128-row half of B
    const int tid  = threadIdx.x;
    const int wid  = tid >> 5;
    const int lane = tid & 31;
    const int r    = lane >> 2;
    const int c    = lane & 3;

    // pair -> (ii <= jj)
    int q = pair, jj = 0;
    while (q >= jj + 1) { q -= (jj + 1); ++jj; }
    const int ii = q;

    // load A (256x64) and B half (128x64), already tf32-rounded bits
    {
        const uint4* gA = (const uint4*)(g_H + (size_t)((jj * NSET + ii) * NHEAD + head) * MITEM * DHEAD);
        const uint4* gB = (const uint4*)(g_H + (size_t)((ii * NSET + jj) * NHEAD + head) * MITEM * DHEAD
                                         + (size_t)nh * 128 * DHEAD);
        #pragma unroll 4
        for (int idx = tid; idx < MITEM * DHEAD / 4; idx += 256) {
            uint4 v = gA[idx];
            int row = idx >> 4, cc = (idx & 15) << 2;
            *(uint4*)&As[row * HSTR + cc] = v;
        }
        #pragma unroll 2
        for (int idx = tid; idx < 128 * DHEAD / 4; idx += 256) {
            uint4 v = gB[idx];
            int row = idx >> 4, cc = (idx & 15) << 2;
            *(uint4*)&Bs[row * HSTR + cc] = v;
        }
    }
    __syncthreads();

    // warp tile: 32 rows x 128 cols; 8 warps cover 256 x 128
    const int wm = wid * 32;

    // resident A fragments: 2 m-tiles x 8 k-steps x 4 regs = 64 regs
    uint32_t aF[2][8][4];
    #pragma unroll
    for (int mt = 0; mt < 2; ++mt)
        #pragma unroll
        for (int ks = 0; ks < 8; ++ks) {
            const uint32_t* base = &As[(wm + mt * 16 + r) * HSTR + ks * 8 + c];
            aF[mt][ks][0] = base[0];
            aF[mt][ks][1] = base[8 * HSTR];
            aF[mt][ks][2] = base[4];
            aF[mt][ks][3] = base[8 * HSTR + 4];
        }

    float sum = 0.f;
    #pragma unroll
    for (int nt = 0; nt < 16; ++nt) {
        uint32_t bF[8][2];
        #pragma unroll
        for (int ks = 0; ks < 8; ++ks) {
            const uint32_t* base = &Bs[(nt * 8 + r) * HSTR + ks * 8 + c];
            bF[ks][0] = base[0];
            bF[ks][1] = base[4];
        }
        #pragma unroll
        for (int mt = 0; mt < 2; ++mt) {
            float cc[4] = {0.f, 0.f, 0.f, 0.f};
            #pragma unroll
            for (int ks = 0; ks < 8; ++ks)
                mma_tf32(cc, aF[mt][ks], bF[ks]);
            #pragma unroll
            for (int e = 0; e < 4; ++e) {
                float v = cc[e];
                sum += (v > 0.f) ? v : 0.3f * v;     // LeakyReLU(0.3)
            }
        }
    }

    // CTA reduce -> deterministic per-half slot
    #pragma unroll
    for (int off = 16; off; off >>= 1)
        sum += __shfl_xor_sync(0xffffffffu, sum, off);
    if (lane == 0) red[wid] = sum;
    __syncthreads();
    if (tid == 0) {
        float t = 0.f;
        #pragma unroll
        for (int w = 0; w < 8; ++w) t += red[w];
        g_scratch[(pair * NHEAD + head) * 2 + nh] = t;
    }
}

// ============================================================================
// Kernel 3: finalize
// ============================================================================
__global__ void finalize_kernel(const float* __restrict__ nItem,
                                const float* __restrict__ W2,
                                float* __restrict__ out)
{
    const int t = threadIdx.x;       // t = j*16 + i
    const int j = t >> 4, i = t & 15;
    const int a = (j > i) ? j : i;
    const int b = (j > i) ? i : j;
    const int p = a * (a + 1) / 2 + b;
    float s = 0.f;
    #pragma unroll
    for (int hh = 0; hh < NHEAD; ++hh) {
        float sh = g_scratch[(p * NHEAD + hh) * 2] + g_scratch[(p * NHEAD + hh) * 2 + 1];
        s += sh * W2[hh];
    }
    out[t] = s / (8.0f * nItem[i] * nItem[j]);   // 8 = sqrt(D=64)
}

// ---------------- entry point ----------------
#define SMEM_K1 ((128 * XSTR + DHEAD * XSTR) * 4)            // 101376
#define SMEM_K2 ((MITEM * HSTR + 128 * HSTR) * 4 + 32)       // 104480

extern "C" void kernel_launch(void* const* d_in, const int* in_sizes, int n_in,
                              void* d_out, int out_size)
{
    const float* x = nullptr;
    const float* nItem = nullptr;
    const float* W1 = nullptr;
    const float* W2 = nullptr;
    for (int k = 0; k < n_in; ++k) {
        switch (in_sizes[k]) {
            case NSET * NSET * MITEM * DIN: x     = (const float*)d_in[k]; break;
            case NSET:                      nItem = (const float*)d_in[k]; break;
            case DIN * NHEAD * DHEAD:       W1    = (const float*)d_in[k]; break;
            case NHEAD:                     W2    = (const float*)d_in[k]; break;
        }
    }

    static bool attr_done = false;
    if (!attr_done) {
        cudaFuncSetAttribute(proj_kernel,
                             cudaFuncAttributeMaxDynamicSharedMemorySize, SMEM_K1);
        cudaFuncSetAttribute(score_kernel,
                             cudaFuncAttributeMaxDynamicSharedMemorySize, SMEM_K2);
        attr_done = true;
    }

    proj_kernel<<<NSET * NSET * 2 * 2, 256, SMEM_K1>>>(x, W1);
    score_kernel<<<NPAIR * NHEAD * 2, 256, SMEM_K2>>>();
    finalize_kernel<<<1, 256>>>(nItem, W2, (float*)d_out);
}

// round 6
// speedup vs baseline: 1.2965x; 1.0069x over previous
#include <cuda_runtime.h>
#include <cuda_bf16.h>
#include <cstdint>

// ---------------------------------------------------------------------------
// cross_set_score, TF32 pipeline (v3: 32-warp proj, 24-warp score):
//  K0: g_W1T = transpose(W1) tf32-rounded (per head, e-major)
//  K1: H[tile,head] = x[tile] @ W1_head   (512-thr CTA, 128 rows x 4 heads)
//  K2: S = sum leakyrelu(A@B^T)           (256-thr CTA, A-half x B-half)
//  K3: out = (S @ W2) / (8 * nItem_i * nItem_j), symmetric fill
// ---------------------------------------------------------------------------

#define NSET  16
#define MITEM 256
#define DIN   128
#define NHEAD 8
#define DHEAD 64
#define NPAIR 136

#define XSTR  132     // 32-bit smem stride for 128-wide tiles (+4 pad)
#define HSTR  68      // 32-bit smem stride for 64-wide tiles  (+4 pad)

__device__ float g_H[NSET * NSET * NHEAD * MITEM * DHEAD];   // 134 MB scratch
__device__ float g_W1T[NHEAD * DHEAD * DIN];                 // 256 KB, [head][e][d]
__device__ float g_scratch[NPAIR * NHEAD * 4];               // 4 quadrant sums

// ---------------- PTX helpers ----------------
__device__ __forceinline__ uint32_t tf32_rna(float v) {
    uint32_t o;
    asm("cvt.rna.tf32.f32 %0, %1;" : "=r"(o) : "f"(v));
    return o;
}
__device__ __forceinline__ void mma_tf32(float* c, const uint32_t* a, const uint32_t* b) {
    asm volatile(
        "mma.sync.aligned.m16n8k8.row.col.f32.tf32.tf32.f32 "
        "{%0,%1,%2,%3}, {%4,%5,%6,%7}, {%8,%9}, {%0,%1,%2,%3};"
        : "+f"(c[0]), "+f"(c[1]), "+f"(c[2]), "+f"(c[3])
        : "r"(a[0]), "r"(a[1]), "r"(a[2]), "r"(a[3]), "r"(b[0]), "r"(b[1]));
}

// ============================================================================
// Kernel 0: transpose + tf32-round W1:  g_W1T[(head*64+e)*128 + d]
// ============================================================================
__global__ void prep_w1(const float* __restrict__ W1)
{
    const int idx = blockIdx.x * 1024 + threadIdx.x;   // 65536 total
    const int he  = idx >> 7;            // head*64 + e
    const int d   = idx & 127;
    g_W1T[idx] = __uint_as_float(tf32_rna(W1[d * (NHEAD * DHEAD) + he]));
}

// ============================================================================
// Kernel 1: projection. grid = 256 tiles * 2 row-halves * 2 head-groups.
// 512 threads, 16 warps (4m x 4n), warp tile 32x16. SMEM ~101KB -> 2 CTA/SM.
// ============================================================================
__global__ __launch_bounds__(512, 2)
void proj_kernel(const float* __restrict__ x)
{
    extern __shared__ uint32_t sm1[];
    uint32_t* xs  = sm1;                    // [128][XSTR]
    uint32_t* w1s = sm1 + 128 * XSTR;       // [64][XSTR]  (one head, e-major)

    const int bx   = blockIdx.x;
    const int tile = bx >> 2;
    const int rh   = (bx >> 1) & 1;
    const int hg   = bx & 1;
    const int tid  = threadIdx.x;
    const int wid  = tid >> 5;
    const int lane = tid & 31;
    const int r    = lane >> 2;
    const int c    = lane & 3;

    // ---- load x half-tile (fp32 -> tf32 bits): 128 x 128 ----
    {
        const float4* g = (const float4*)(x + ((size_t)tile * MITEM + rh * 128) * DIN);
        #pragma unroll
        for (int it = 0; it < 8; ++it) {
            int idx = tid + it * 512;
            float4 v = g[idx];
            int row = idx >> 5, cc = (idx & 31) << 2;
            uint32_t* d = &xs[row * XSTR + cc];
            d[0] = tf32_rna(v.x); d[1] = tf32_rna(v.y);
            d[2] = tf32_rna(v.z); d[3] = tf32_rna(v.w);
        }
    }

    // ---- stage W1 head slice: straight uint4 copy (2048 uint4) ----
    {
        const uint4* w1g = (const uint4*)(g_W1T + (size_t)(hg * 4) * DHEAD * DIN);
        #pragma unroll
        for (int it = 0; it < 4; ++it) {
            int idx = tid + it * 512;
            int e = idx >> 5, dq = idx & 31;
            *(uint4*)&w1s[e * XSTR + dq * 4] = w1g[idx];
        }
    }
    __syncthreads();

    const int wm = (wid & 3) * 32;
    const int wn = (wid >> 2) * 16;

    #pragma unroll 1
    for (int h = 0; h < 4; ++h) {
        const int head = hg * 4 + h;

        float acc[2][2][4];
        #pragma unroll
        for (int mt = 0; mt < 2; ++mt)
            #pragma unroll
            for (int nt = 0; nt < 2; ++nt)
                #pragma unroll
                for (int e = 0; e < 4; ++e) acc[mt][nt][e] = 0.f;

        #pragma unroll
        for (int ks = 0; ks < 16; ++ks) {
            const int k0 = ks * 8;
            uint32_t af[2][4], bf[2][2];
            #pragma unroll
            for (int mt = 0; mt < 2; ++mt) {
                const uint32_t* base = &xs[(wm + mt * 16 + r) * XSTR + k0 + c];
                af[mt][0] = base[0];
                af[mt][1] = base[8 * XSTR];
                af[mt][2] = base[4];
                af[mt][3] = base[8 * XSTR + 4];
            }
            #pragma unroll
            for (int nt = 0; nt < 2; ++nt) {
                const uint32_t* base = &w1s[(wn + nt * 8 + r) * XSTR + k0 + c];
                bf[nt][0] = base[0];
                bf[nt][1] = base[4];
            }
            #pragma unroll
            for (int mt = 0; mt < 2; ++mt)
                #pragma unroll
                for (int nt = 0; nt < 2; ++nt)
                    mma_tf32(acc[mt][nt], af[mt], bf[nt]);
        }

        float* Hout = g_H + (size_t)(tile * NHEAD + head) * MITEM * DHEAD;
        #pragma unroll
        for (int mt = 0; mt < 2; ++mt)
            #pragma unroll
            for (int nt = 0; nt < 2; ++nt) {
                int row = rh * 128 + wm + mt * 16 + r;
                int col = wn + nt * 8 + c * 2;
                float2 lo = { __uint_as_float(tf32_rna(acc[mt][nt][0])),
                              __uint_as_float(tf32_rna(acc[mt][nt][1])) };
                float2 hi = { __uint_as_float(tf32_rna(acc[mt][nt][2])),
                              __uint_as_float(tf32_rna(acc[mt][nt][3])) };
                *(float2*)&Hout[row * DHEAD + col]       = lo;
                *(float2*)&Hout[(row + 8) * DHEAD + col] = hi;
            }

        if (h < 3) {
            __syncthreads();
            const uint4* w1gn = (const uint4*)(g_W1T + (size_t)(head + 1) * DHEAD * DIN);
            #pragma unroll
            for (int it = 0; it < 4; ++it) {
                int idx = tid + it * 512;
                int e = idx >> 5, dq = idx & 31;
                *(uint4*)&w1s[e * XSTR + dq * 4] = w1gn[idx];
            }
            __syncthreads();
        }
    }
}

// ============================================================================
// Kernel 2: score. grid = 136 pairs * 8 heads * 2 A-halves * 2 B-halves.
// 256 threads, 8 warps, warp tile 16x128. SMEM ~70KB -> 3 CTA/SM.
// ============================================================================
__global__ __launch_bounds__(256, 3)
void score_kernel()
{
    extern __shared__ uint32_t sm2[];
    uint32_t* As  = sm2;                          // [128][HSTR]
    uint32_t* Bs  = sm2 + 128 * HSTR;             // [128][HSTR]
    float*    red = (float*)(sm2 + 2 * 128 * HSTR);   // [8]

    const int bx   = blockIdx.x;
    const int pair = bx >> 5;
    const int head = (bx >> 2) & 7;
    const int ah   = (bx >> 1) & 1;
    const int bh   = bx & 1;
    const int tid  = threadIdx.x;
    const int wid  = tid >> 5;
    const int lane = tid & 31;
    const int r    = lane >> 2;
    const int c    = lane & 3;

    // pair -> (ii <= jj)
    int q = pair, jj = 0;
    while (q >= jj + 1) { q -= (jj + 1); ++jj; }
    const int ii = q;

    // load A half (128x64) and B half (128x64)
    {
        const uint4* gA = (const uint4*)(g_H + (size_t)((jj * NSET + ii) * NHEAD + head) * MITEM * DHEAD
                                         + (size_t)ah * 128 * DHEAD);
        const uint4* gB = (const uint4*)(g_H + (size_t)((ii * NSET + jj) * NHEAD + head) * MITEM * DHEAD
                                         + (size_t)bh * 128 * DHEAD);
        #pragma unroll
        for (int it = 0; it < 8; ++it) {
            int idx = tid + it * 256;
            uint4 va = gA[idx];
            uint4 vb = gB[idx];
            int row = idx >> 4, cc = (idx & 15) << 2;
            *(uint4*)&As[row * HSTR + cc] = va;
            *(uint4*)&Bs[row * HSTR + cc] = vb;
        }
    }
    __syncthreads();

    // warp tile: 16 rows x 128 cols
    const int wm = wid * 16;

    // resident A fragments: 8 k-steps x 4 regs = 32 regs
    uint32_t aF[8][4];
    #pragma unroll
    for (int ks = 0; ks < 8; ++ks) {
        const uint32_t* base = &As[(wm + r) * HSTR + ks * 8 + c];
        aF[ks][0] = base[0];
        aF[ks][1] = base[8 * HSTR];
        aF[ks][2] = base[4];
        aF[ks][3] = base[8 * HSTR + 4];
    }

    float sum = 0.f;
    #pragma unroll
    for (int nt = 0; nt < 16; ++nt) {
        uint32_t bF[8][2];
        #pragma unroll
        for (int ks = 0; ks < 8; ++ks) {
            const uint32_t* base = &Bs[(nt * 8 + r) * HSTR + ks * 8 + c];
            bF[ks][0] = base[0];
            bF[ks][1] = base[4];
        }
        float cc4[4] = {0.f, 0.f, 0.f, 0.f};
        #pragma unroll
        for (int ks = 0; ks < 8; ++ks)
            mma_tf32(cc4, aF[ks], bF[ks]);
        #pragma unroll
        for (int e = 0; e < 4; ++e) {
            float v = cc4[e];
            sum += (v > 0.f) ? v : 0.3f * v;     // LeakyReLU(0.3)
        }
    }

    // CTA reduce -> deterministic quadrant slot
    #pragma unroll
    for (int off = 16; off; off >>= 1)
        sum += __shfl_xor_sync(0xffffffffu, sum, off);
    if (lane == 0) red[wid] = sum;
    __syncthreads();
    if (tid == 0) {
        float t = 0.f;
        #pragma unroll
        for (int w = 0; w < 8; ++w) t += red[w];
        g_scratch[((pair * NHEAD + head) * 2 + ah) * 2 + bh] = t;
    }
}

// ============================================================================
// Kernel 3: finalize
// ============================================================================
__global__ void finalize_kernel(const float* __restrict__ nItem,
                                const float* __restrict__ W2,
                                float* __restrict__ out)
{
    const int t = threadIdx.x;       // t = j*16 + i
    const int j = t >> 4, i = t & 15;
    const int a = (j > i) ? j : i;
    const int b = (j > i) ? i : j;
    const int p = a * (a + 1) / 2 + b;
    float s = 0.f;
    #pragma unroll
    for (int hh = 0; hh < NHEAD; ++hh) {
        const float* q = &g_scratch[(p * NHEAD + hh) * 4];
        s += (q[0] + q[1] + q[2] + q[3]) * W2[hh];
    }
    out[t] = s / (8.0f * nItem[i] * nItem[j]);   // 8 = sqrt(D=64)
}

// ---------------- entry point ----------------
#define SMEM_K1 ((128 * XSTR + DHEAD * XSTR) * 4)            // 101376
#define SMEM_K2 ((2 * 128 * HSTR) * 4 + 32)                  // 69664

extern "C" void kernel_launch(void* const* d_in, const int* in_sizes, int n_in,
                              void* d_out, int out_size)
{
    const float* x = nullptr;
    const float* nItem = nullptr;
    const float* W1 = nullptr;
    const float* W2 = nullptr;
    for (int k = 0; k < n_in; ++k) {
        switch (in_sizes[k]) {
            case NSET * NSET * MITEM * DIN: x     = (const float*)d_in[k]; break;
            case NSET:                      nItem = (const float*)d_in[k]; break;
            case DIN * NHEAD * DHEAD:       W1    = (const float*)d_in[k]; break;
            case NHEAD:                     W2    = (const float*)d_in[k]; break;
        }
    }

    static bool attr_done = false;
    if (!attr_done) {
        cudaFuncSetAttribute(proj_kernel,
                             cudaFuncAttributeMaxDynamicSharedMemorySize, SMEM_K1);
        cudaFuncSetAttribute(score_kernel,
                             cudaFuncAttributeMaxDynamicSharedMemorySize, SMEM_K2);
        attr_done = true;
    }

    prep_w1<<<64, 1024>>>(W1);
    proj_kernel<<<NSET * NSET * 2 * 2, 512, SMEM_K1>>>(x);
    score_kernel<<<NPAIR * NHEAD * 4, 256, SMEM_K2>>>();
    finalize_kernel<<<1, 256>>>(nItem, W2, (float*)d_out);
}